// round 14
// baseline (speedup 1.0000x reference)
#include <cuda_runtime.h>
#include <cuda_fp16.h>
#include <cstdint>
#include <cstddef>

// Shapes (fixed by the problem)
#define L_DIM   2
#define BAT     32
#define A_DIM   64
#define B_DIM   1024
#define D_DIM   128
#define NBITS   1024

#define T_DOC   512           // doc m-tiles
#define T_ALL   544           // + 32 query m-tiles
#define GRID_Y  18

// Packed sign codes: 32 uint32 words per row (1024 bits)
__device__ unsigned g_codes_q[L_DIM * BAT * A_DIM * (NBITS / 32)];
__device__ unsigned g_codes_d[L_DIM * BAT * B_DIM * (NBITS / 32)];

// f16(hi-only) arrays, fragment-permuted. Per row (128 halfs = 64 words):
//   [ksp(4)][tq(4)] uint4 = { ks0:hi2[tq], ks0:hi2[tq+4], ks1:hi2[tq], ks1:hi2[tq+4] }
__device__ uint32_t g_half_q[(size_t)4096 * 64];
__device__ uint32_t g_half_d[(size_t)65536 * 64];
__device__ uint32_t g_half_r[(size_t)1024 * 64];

// ---------------------------------------------------------------------------
__device__ __forceinline__ uint32_t smem_u32(const void* p) {
    uint32_t a;
    asm("{ .reg .u64 t; cvta.to.shared.u64 t, %1; cvt.u32.u64 %0, t; }"
        : "=r"(a) : "l"(p));
    return a;
}
__device__ __forceinline__ void cpa16(uint32_t saddr, const void* g) {
    asm volatile("cp.async.ca.shared.global [%0], [%1], 16;"
                 :: "r"(saddr), "l"(g) : "memory");
}
#define CP_COMMIT() asm volatile("cp.async.commit_group;" ::: "memory")
#define CP_WAIT2()  asm volatile("cp.async.wait_group 2;" ::: "memory")
#define CP_WAIT1()  asm volatile("cp.async.wait_group 1;" ::: "memory")
#define CP_WAIT0()  asm volatile("cp.async.wait_group 0;" ::: "memory")

// m16n8k16 f16 x f16 -> f32
__device__ __forceinline__ void mma_f16(float c[4],
                                        uint32_t a0, uint32_t a1, uint32_t a2, uint32_t a3,
                                        uint32_t b0, uint32_t b1) {
    asm volatile("mma.sync.aligned.m16n8k16.row.col.f32.f16.f16.f32 "
                 "{%0,%1,%2,%3}, {%4,%5,%6,%7}, {%8,%9}, {%0,%1,%2,%3};"
                 : "+f"(c[0]), "+f"(c[1]), "+f"(c[2]), "+f"(c[3])
                 : "r"(a0), "r"(a1), "r"(a2), "r"(a3), "r"(b0), "r"(b1));
}

// ---------------------------------------------------------------------------
// Pre-convert: fp32 -> f16 in fragment-permuted layout (hi only).
// ---------------------------------------------------------------------------
__global__ void split_kernel(const float* __restrict__ src,
                             uint32_t* __restrict__ dst, int total)
{
    int idx = blockIdx.x * blockDim.x + threadIdx.x;
    if (idx >= total) return;
    int row = idx >> 2, ksp = idx & 3;
    const float4* p = (const float4*)(src + (size_t)row * D_DIM + ksp * 32);
    float f[32];
#pragma unroll
    for (int q = 0; q < 8; q++) {
        float4 v = p[q];
        f[q * 4 + 0] = v.x; f[q * 4 + 1] = v.y;
        f[q * 4 + 2] = v.z; f[q * 4 + 3] = v.w;
    }
    uint32_t h0[8], h1[8];
#pragma unroll
    for (int j = 0; j < 8; j++) {
        __half2 a = __halves2half2(__float2half_rn(f[2 * j]),
                                   __float2half_rn(f[2 * j + 1]));
        __half2 b = __halves2half2(__float2half_rn(f[16 + 2 * j]),
                                   __float2half_rn(f[16 + 2 * j + 1]));
        h0[j] = *(uint32_t*)&a;
        h1[j] = *(uint32_t*)&b;
    }
    uint4* o = (uint4*)(dst + (size_t)row * 64 + ksp * 16);
#pragma unroll
    for (int t = 0; t < 4; t++)
        o[t] = make_uint4(h0[t], h0[t + 4], h1[t], h1[t + 4]);
}

// ---------------------------------------------------------------------------
// Combined doc+query hh-only f16 GEMM, 4-stage A pipeline (1 sync/tile),
// ballot-gated sparse fp32 refinement, sign-pack epilogue.
// ---------------------------------------------------------------------------
#define ROWB  320                   // smem row stride (256B data + 64 pad)
#define TILEB (128 * ROWB)          // 40960
#define SM_A  TILEB                 // stage s at SM_A + s*TILEB, s=0..3
#define QOFF  (SM_A + 4 * TILEB)
#define QCAP  3072
#define SMEMSZ (QOFF + 16 + QCAP * 4)

#define TAU 2.5e-3f

__global__ __launch_bounds__(512, 1)
void lsh_hh_kernel(const uint32_t* __restrict__ Ahd,
                   const uint32_t* __restrict__ Ahq,
                   const float* __restrict__ Afd,
                   const float* __restrict__ Afq,
                   const uint32_t* __restrict__ Bh,
                   const float* __restrict__ Bf,
                   unsigned* __restrict__ codes_d,
                   unsigned* __restrict__ codes_q)
{
    extern __shared__ char smem[];
    const uint32_t sb = smem_u32(smem);
    const int t    = threadIdx.x;
    const int wid  = t >> 5, lane = t & 31;
    const int g    = lane >> 2, tq = lane & 3;
    const int wm   = wid >> 2, wn = wid & 3;     // 4x4 warp grid
    const int n_tile = blockIdx.x;

    int* qcnt = (int*)(smem + QOFF);
    uint32_t* qbuf = (uint32_t*)(smem + QOFF + 16);
    if (t == 0) *qcnt = 0;

    // ---- B resident copy: 128 rows x 256B (own commit group) ----
    {
        const uint32_t* bg = Bh + (size_t)n_tile * 128 * 64;
#pragma unroll
        for (int i = 0; i < 4; i++) {
            int gi = t + 512 * i, row = gi >> 4, w = gi & 15;
            cpa16(sb + row * ROWB + w * 16, bg + (size_t)row * 64 + w * 4);
        }
        CP_COMMIT();
    }

    auto a_ptr = [&](int ti) {
        return (ti < T_DOC) ? Ahd + (size_t)ti * 8192
                            : Ahq + (size_t)(ti - T_DOC) * 8192;
    };
    auto issueA = [&](int ti, int st) {
        const uint32_t* ag = a_ptr(ti);
        uint32_t dst = sb + SM_A + st * TILEB;
#pragma unroll
        for (int i = 0; i < 4; i++) {
            int gi = t + 512 * i, row = gi >> 4, w = gi & 15;
            cpa16(dst + row * ROWB + w * 16, ag + (size_t)row * 64 + w * 4);
        }
        CP_COMMIT();
    };

    // prologue: stages 0,1 = first two tiles
    {
        int t0 = blockIdx.y;
        if (t0 < T_ALL)          issueA(t0, 0);
        if (t0 + GRID_Y < T_ALL) issueA(t0 + GRID_Y, 1);
    }

    int it = 0;
    for (int ti = blockIdx.y; ti < T_ALL; ti += GRID_Y, it++) {
        const int stage = it & 3;
        const int pf = ti + 2 * GRID_Y;
        if (pf < T_ALL) { issueA(pf, (it + 2) & 3); CP_WAIT2(); }
        else if (ti + GRID_Y < T_ALL) CP_WAIT1();
        else                          CP_WAIT0();
        __syncthreads();   // stage data visible; also fences prior epilogue vs stage reuse

        float C[2][4][4];
#pragma unroll
        for (int i = 0; i < 2; i++)
#pragma unroll
            for (int j = 0; j < 4; j++)
#pragma unroll
                for (int k = 0; k < 4; k++) C[i][j][k] = 0.0f;

        const char* abase0 = smem + SM_A + stage * TILEB;
#pragma unroll
        for (int ksp = 0; ksp < 4; ksp++) {
            uint4 B4[4], A4[2][2];
#pragma unroll
            for (int nf = 0; nf < 4; nf++) {
                int n = wn * 32 + nf * 8 + g;
                B4[nf] = *(const uint4*)(smem + n * ROWB + ksp * 64 + tq * 16);
            }
#pragma unroll
            for (int mf = 0; mf < 2; mf++) {
                int r0 = wm * 32 + mf * 16 + g;
                const char* base = abase0 + ksp * 64 + tq * 16;
                A4[mf][0] = *(const uint4*)(base + r0 * ROWB);
                A4[mf][1] = *(const uint4*)(base + (r0 + 8) * ROWB);
            }
#pragma unroll
            for (int mf = 0; mf < 2; mf++)
#pragma unroll
                for (int nf = 0; nf < 4; nf++)
                    mma_f16(C[mf][nf],
                            A4[mf][0].x, A4[mf][1].x, A4[mf][0].y, A4[mf][1].y,
                            B4[nf].x, B4[nf].y);
#pragma unroll
            for (int mf = 0; mf < 2; mf++)
#pragma unroll
                for (int nf = 0; nf < 4; nf++)
                    mma_f16(C[mf][nf],
                            A4[mf][0].z, A4[mf][1].z, A4[mf][0].w, A4[mf][1].w,
                            B4[nf].z, B4[nf].w);
        }

        const bool isq = (ti >= T_DOC);
        const int rowbase = (isq ? (ti - T_DOC) : ti) * 128;
        unsigned* codes = isq ? codes_q : codes_d;

        // ---- flag fast path: fmin(|.|) tree + warp vote; slow scan is rare ----
#pragma unroll
        for (int mf = 0; mf < 2; mf++) {
            float mn = fabsf(C[mf][0][0]);
#pragma unroll
            for (int nf = 0; nf < 4; nf++)
#pragma unroll
                for (int idx = 0; idx < 4; idx++)
                    mn = fminf(mn, fabsf(C[mf][nf][idx]));
            if (__any_sync(0xffffffffu, mn < TAU)) {
#pragma unroll
                for (int nf = 0; nf < 4; nf++)
#pragma unroll
                    for (int idx = 0; idx < 4; idx++) {
                        if (fabsf(C[mf][nf][idx]) < TAU) {
                            int row = rowbase + wm * 32 + mf * 16 + g + ((idx >> 1) ? 8 : 0);
                            int col = n_tile * 128 + wn * 32 + nf * 8 + tq * 2 + (idx & 1);
                            int qi = atomicAdd(qcnt, 1);
                            if (qi < QCAP)
                                qbuf[qi] = ((uint32_t)isq << 31) |
                                           ((uint32_t)row << 10) | (uint32_t)col;
                        }
                    }
            }
        }

        // ---- provisional sign-pack via shfl-OR over the 4 t-lanes ----
#pragma unroll
        for (int mf = 0; mf < 2; mf++) {
            unsigned m0 = 0, m1 = 0;
#pragma unroll
            for (int nf = 0; nf < 4; nf++) {
                int p = nf * 8 + tq * 2;
                m0 |= (C[mf][nf][0] > 0.0f ? 1u : 0u) << p;
                m0 |= (C[mf][nf][1] > 0.0f ? 1u : 0u) << (p + 1);
                m1 |= (C[mf][nf][2] > 0.0f ? 1u : 0u) << p;
                m1 |= (C[mf][nf][3] > 0.0f ? 1u : 0u) << (p + 1);
            }
            m0 |= __shfl_xor_sync(0xffffffffu, m0, 1);
            m0 |= __shfl_xor_sync(0xffffffffu, m0, 2);
            m1 |= __shfl_xor_sync(0xffffffffu, m1, 1);
            m1 |= __shfl_xor_sync(0xffffffffu, m1, 2);
            if (tq == 0) {
                size_t r0 = (size_t)rowbase + wm * 32 + mf * 16 + g;
                int wcol = n_tile * 4 + wn;
                codes[r0 * 32 + wcol]       = m0;
                codes[(r0 + 8) * 32 + wcol] = m1;
            }
        }
        // no trailing sync: 4-stage pipeline + next iteration's barrier protect reuse
    }

    // ---- refinement: exact fp32 dot for queued elements, patch bits ----
    __threadfence();
    __syncthreads();
    int nq = *qcnt; if (nq > QCAP) nq = QCAP;
    for (int i = t; i < nq; i += 512) {
        uint32_t e = qbuf[i];
        int isq2 = (int)(e >> 31);
        int row = (int)((e >> 10) & 0xFFFFu), col = (int)(e & 1023u);
        const float* Af = isq2 ? Afq : Afd;
        unsigned* codes = isq2 ? codes_q : codes_d;
        const float4* pa = (const float4*)(Af + (size_t)row * D_DIM);
        const float4* pb = (const float4*)(Bf + (size_t)col * D_DIM);
        float d = 0.0f;
#pragma unroll 8
        for (int w = 0; w < 32; w++) {
            float4 x = pa[w], y = pb[w];
            d += x.x * y.x + x.y * y.y + x.z * y.z + x.w * y.w;
        }
        unsigned* wp = codes + (size_t)row * 32 + (col >> 5);
        unsigned bit = 1u << (col & 31);
        if (d > 0.0f) atomicOr(wp, bit);
        else          atomicAnd(wp, ~bit);
    }
}

// ---------------------------------------------------------------------------
// popcount Hamming -> cos -> masked output in [BAT,L,A,B] layout. (unchanged)
// ---------------------------------------------------------------------------
__global__ __launch_bounds__(256)
void simmat_kernel(const int* __restrict__ qtok,
                   const int* __restrict__ dtok,
                   float* __restrict__ out)
{
    __shared__ unsigned qw[A_DIM][33];
    __shared__ unsigned dw[64][33];
    __shared__ int s1[A_DIM];
    __shared__ int s2[64];
    __shared__ int qm[A_DIM];
    __shared__ int dm[64];

    const int t  = threadIdx.x;
    const int cc = blockIdx.x;
    const int b  = blockIdx.y;
    const int l  = blockIdx.z;

    const unsigned* qbase = g_codes_q + (size_t)(l * BAT + b) * A_DIM * 32;
    const unsigned* dbase = g_codes_d +
        ((size_t)(l * BAT + b) * B_DIM + (size_t)cc * 64) * 32;

#pragma unroll
    for (int f = t; f < 64 * 32; f += 256) {
        int row = f >> 5, w = f & 31;
        qw[row][w] = qbase[f];
        dw[row][w] = dbase[f];
    }
    if (t < 64)        qm[t]      = qtok[b * A_DIM + t];
    else if (t < 128)  dm[t - 64] = dtok[b * B_DIM + cc * 64 + (t - 64)];
    __syncthreads();

    if (t < 64) {
        int s = 0;
#pragma unroll
        for (int w = 0; w < 32; w++) s += __popc(qw[t][w]);
        s1[t] = s;
    } else if (t < 128) {
        int s = 0;
#pragma unroll
        for (int w = 0; w < 32; w++) s += __popc(dw[t - 64][w]);
        s2[t - 64] = s;
    }
    __syncthreads();

    const int ta = t >> 4;
    const int tc = t & 15;
    int dot[4][4];
#pragma unroll
    for (int ai = 0; ai < 4; ai++)
#pragma unroll
        for (int ci = 0; ci < 4; ci++) dot[ai][ci] = 0;

#pragma unroll
    for (int w = 0; w < 32; w++) {
        unsigned qa[4], dc[4];
#pragma unroll
        for (int ai = 0; ai < 4; ai++) qa[ai] = qw[ta + 16 * ai][w];
#pragma unroll
        for (int ci = 0; ci < 4; ci++) dc[ci] = dw[tc + 16 * ci][w];
#pragma unroll
        for (int ai = 0; ai < 4; ai++)
#pragma unroll
            for (int ci = 0; ci < 4; ci++)
                dot[ai][ci] += __popc(qa[ai] & dc[ci]);
    }

    const float kfac = 3.14159265358979323846f / (float)NBITS;
#pragma unroll
    for (int ai = 0; ai < 4; ai++) {
        int a = ta + 16 * ai;
        bool qz = (qm[a] == 0);
        int  sa = s1[a];
        size_t obase = ((((size_t)b * L_DIM + l) * A_DIM + a) * B_DIM)
                       + (size_t)cc * 64;
#pragma unroll
        for (int ci = 0; ci < 4; ci++) {
            int c   = tc + 16 * ci;
            int ham = sa + s2[c] - 2 * dot[ai][ci];
            float v = (qz || dm[c] == 0) ? 0.0f
                                         : __cosf(kfac * (float)ham);
            out[obase + c] = v;
        }
    }
}

// ---------------------------------------------------------------------------
extern "C" void kernel_launch(void* const* d_in, const int* in_sizes, int n_in,
                              void* d_out, int out_size)
{
    const float* qe = (const float*)d_in[0];
    const float* de = (const float*)d_in[1];
    const int*   qt = (const int*)d_in[2];
    const int*   dt = (const int*)d_in[3];
    const float* r  = (const float*)d_in[4];
    float* out = (float*)d_out;

    unsigned *cq = nullptr, *cd = nullptr;
    uint32_t *hq = nullptr, *hd = nullptr, *hr = nullptr;
    cudaGetSymbolAddress((void**)&cq, g_codes_q);
    cudaGetSymbolAddress((void**)&cd, g_codes_d);
    cudaGetSymbolAddress((void**)&hq, g_half_q);
    cudaGetSymbolAddress((void**)&hd, g_half_d);
    cudaGetSymbolAddress((void**)&hr, g_half_r);

    // fp32 -> f16 (fragment-permuted); one thread per (row, ksp)
    split_kernel<<<(4096 * 4 + 255) / 256, 256>>>(qe, hq, 4096 * 4);
    split_kernel<<<(65536 * 4 + 255) / 256, 256>>>(de, hd, 65536 * 4);
    split_kernel<<<(1024 * 4 + 255) / 256, 256>>>(r, hr, 1024 * 4);

    cudaFuncSetAttribute(lsh_hh_kernel,
                         cudaFuncAttributeMaxDynamicSharedMemorySize, SMEMSZ);

    // one combined launch: 544 tiles (512 doc + 32 query), 8 n-slices x 18 CTAs
    lsh_hh_kernel<<<dim3(8, GRID_Y), 512, SMEMSZ>>>(hd, hq, de, qe, hr, r, cd, cq);

    simmat_kernel<<<dim3(B_DIM / 64, BAT, L_DIM), 256>>>(qt, dt, out);
}

// round 16
// speedup vs baseline: 1.0039x; 1.0039x over previous
#include <cuda_runtime.h>
#include <cuda_fp16.h>
#include <cstdint>
#include <cstddef>

// Shapes (fixed by the problem)
#define L_DIM   2
#define BAT     32
#define A_DIM   64
#define B_DIM   1024
#define D_DIM   128
#define NBITS   1024

#define T_DOC   512           // doc m-tiles
#define T_ALL   544           // + 32 query m-tiles
#define NSL     4             // n-slices of 256 cols
#define GRID_Y  36

// Packed sign codes: 32 uint32 words per row (1024 bits)
__device__ unsigned g_codes_q[L_DIM * BAT * A_DIM * (NBITS / 32)];
__device__ unsigned g_codes_d[L_DIM * BAT * B_DIM * (NBITS / 32)];

// f16(hi-only) arrays, fragment-permuted. Per row (128 halfs = 64 words):
//   [ksp(4)][tq(4)] uint4 = { ks0:hi2[tq], ks0:hi2[tq+4], ks1:hi2[tq], ks1:hi2[tq+4] }
__device__ uint32_t g_half_q[(size_t)4096 * 64];
__device__ uint32_t g_half_d[(size_t)65536 * 64];
__device__ uint32_t g_half_r[(size_t)1024 * 64];

// ---------------------------------------------------------------------------
__device__ __forceinline__ uint32_t smem_u32(const void* p) {
    uint32_t a;
    asm("{ .reg .u64 t; cvta.to.shared.u64 t, %1; cvt.u32.u64 %0, t; }"
        : "=r"(a) : "l"(p));
    return a;
}
__device__ __forceinline__ void cpa16(uint32_t saddr, const void* g) {
    asm volatile("cp.async.ca.shared.global [%0], [%1], 16;"
                 :: "r"(saddr), "l"(g) : "memory");
}
#define CP_COMMIT() asm volatile("cp.async.commit_group;" ::: "memory")
#define CP_WAIT1()  asm volatile("cp.async.wait_group 1;" ::: "memory")
#define CP_WAIT0()  asm volatile("cp.async.wait_group 0;" ::: "memory")

// m16n8k16 f16 x f16 -> f32
__device__ __forceinline__ void mma_f16(float c[4],
                                        uint32_t a0, uint32_t a1, uint32_t a2, uint32_t a3,
                                        uint32_t b0, uint32_t b1) {
    asm volatile("mma.sync.aligned.m16n8k16.row.col.f32.f16.f16.f32 "
                 "{%0,%1,%2,%3}, {%4,%5,%6,%7}, {%8,%9}, {%0,%1,%2,%3};"
                 : "+f"(c[0]), "+f"(c[1]), "+f"(c[2]), "+f"(c[3])
                 : "r"(a0), "r"(a1), "r"(a2), "r"(a3), "r"(b0), "r"(b1));
}

// ---------------------------------------------------------------------------
// Pre-convert: fp32 -> f16 in fragment-permuted layout (hi only).
// ---------------------------------------------------------------------------
__global__ void split_kernel(const float* __restrict__ src,
                             uint32_t* __restrict__ dst, int total)
{
    int idx = blockIdx.x * blockDim.x + threadIdx.x;
    if (idx >= total) return;
    int row = idx >> 2, ksp = idx & 3;
    const float4* p = (const float4*)(src + (size_t)row * D_DIM + ksp * 32);
    float f[32];
#pragma unroll
    for (int q = 0; q < 8; q++) {
        float4 v = p[q];
        f[q * 4 + 0] = v.x; f[q * 4 + 1] = v.y;
        f[q * 4 + 2] = v.z; f[q * 4 + 3] = v.w;
    }
    uint32_t h0[8], h1[8];
#pragma unroll
    for (int j = 0; j < 8; j++) {
        __half2 a = __halves2half2(__float2half_rn(f[2 * j]),
                                   __float2half_rn(f[2 * j + 1]));
        __half2 b = __halves2half2(__float2half_rn(f[16 + 2 * j]),
                                   __float2half_rn(f[16 + 2 * j + 1]));
        h0[j] = *(uint32_t*)&a;
        h1[j] = *(uint32_t*)&b;
    }
    uint4* o = (uint4*)(dst + (size_t)row * 64 + ksp * 16);
#pragma unroll
    for (int t = 0; t < 4; t++)
        o[t] = make_uint4(h0[t], h0[t + 4], h1[t], h1[t + 4]);
}

// ---------------------------------------------------------------------------
// 128m x 256n macro-tile hh GEMM: 256 R-rows resident, A streamed once per
// 256 output cols (halves LDGSTS pressure per MMA). Two sequential n-halves
// per tile for register reuse. 3-stage A pipeline, issue after barrier.
// ---------------------------------------------------------------------------
#define ROWB  320                    // smem row stride (256B data + 64 pad)
#define SM_B_SZ (256 * ROWB)         // 81920 (two 128-col B slices)
#define TILEB (128 * ROWB)           // 40960
#define SM_A  SM_B_SZ                // stages 0..2
#define QOFF  (SM_A + 3 * TILEB)     // 204800
#define QCAP  3072
#define SMEMSZ (QOFF + 16 + QCAP * 4)

#define TAU 2.5e-3f

__global__ __launch_bounds__(512, 1)
void lsh_hh_kernel(const uint32_t* __restrict__ Ahd,
                   const uint32_t* __restrict__ Ahq,
                   const float* __restrict__ Afd,
                   const float* __restrict__ Afq,
                   const uint32_t* __restrict__ Bh,
                   const float* __restrict__ Bf,
                   unsigned* __restrict__ codes_d,
                   unsigned* __restrict__ codes_q)
{
    extern __shared__ char smem[];
    const uint32_t sb = smem_u32(smem);
    const int t    = threadIdx.x;
    const int wid  = t >> 5, lane = t & 31;
    const int g    = lane >> 2, tq = lane & 3;
    const int wm   = wid >> 2, wn = wid & 3;     // 4x4 warp grid
    const int n_tile = blockIdx.x;               // 0..3, 256 cols each

    int* qcnt = (int*)(smem + QOFF);
    uint32_t* qbuf = (uint32_t*)(smem + QOFF + 16);
    if (t == 0) *qcnt = 0;

    // ---- B resident copy: 256 rows x 256B (own commit group) ----
    {
        const uint32_t* bg = Bh + (size_t)n_tile * 256 * 64;
#pragma unroll
        for (int i = 0; i < 8; i++) {
            int gi = t + 512 * i, row = gi >> 4, w = gi & 15;
            cpa16(sb + row * ROWB + w * 16, bg + (size_t)row * 64 + w * 4);
        }
        CP_COMMIT();
    }

    auto a_ptr = [&](int ti) {
        return (ti < T_DOC) ? Ahd + (size_t)ti * 8192
                            : Ahq + (size_t)(ti - T_DOC) * 8192;
    };
    auto issueA = [&](int ti, int st) {
        const uint32_t* ag = a_ptr(ti);
        uint32_t dst = sb + SM_A + st * TILEB;
#pragma unroll
        for (int i = 0; i < 4; i++) {
            int gi = t + 512 * i, row = gi >> 4, w = gi & 15;
            cpa16(dst + row * ROWB + w * 16, ag + (size_t)row * 64 + w * 4);
        }
        CP_COMMIT();
    };

    // prologue: stages 0,1 = first two tiles
    {
        int t0 = blockIdx.y;
        if (t0 < T_ALL)          issueA(t0, 0);
        if (t0 + GRID_Y < T_ALL) issueA(t0 + GRID_Y, 1);
    }

    int it = 0;
    for (int ti = blockIdx.y; ti < T_ALL; ti += GRID_Y, it++) {
        const int stage = it % 3;
        if (ti + GRID_Y < T_ALL) CP_WAIT1(); else CP_WAIT0();
        __syncthreads();   // stage data visible; prior-iter reads of stage (it+2)%3 done
        if (ti + 2 * GRID_Y < T_ALL) issueA(ti + 2 * GRID_Y, (it + 2) % 3);

        const bool isq = (ti >= T_DOC);
        const int rowbase = (isq ? (ti - T_DOC) : ti) * 128;
        unsigned* codes = isq ? codes_q : codes_d;
        const char* abase0 = smem + SM_A + stage * TILEB;

#pragma unroll
        for (int h = 0; h < 2; h++) {          // two 128-col halves
            float C[2][4][4];
#pragma unroll
            for (int i = 0; i < 2; i++)
#pragma unroll
                for (int j = 0; j < 4; j++)
#pragma unroll
                    for (int k = 0; k < 4; k++) C[i][j][k] = 0.0f;

#pragma unroll
            for (int ksp = 0; ksp < 4; ksp++) {
                uint4 B4[4], A4[2][2];
#pragma unroll
                for (int nf = 0; nf < 4; nf++) {
                    int n = h * 128 + wn * 32 + nf * 8 + g;
                    B4[nf] = *(const uint4*)(smem + n * ROWB + ksp * 64 + tq * 16);
                }
#pragma unroll
                for (int mf = 0; mf < 2; mf++) {
                    int r0 = wm * 32 + mf * 16 + g;
                    const char* base = abase0 + ksp * 64 + tq * 16;
                    A4[mf][0] = *(const uint4*)(base + r0 * ROWB);
                    A4[mf][1] = *(const uint4*)(base + (r0 + 8) * ROWB);
                }
#pragma unroll
                for (int mf = 0; mf < 2; mf++)
#pragma unroll
                    for (int nf = 0; nf < 4; nf++)
                        mma_f16(C[mf][nf],
                                A4[mf][0].x, A4[mf][1].x, A4[mf][0].y, A4[mf][1].y,
                                B4[nf].x, B4[nf].y);
#pragma unroll
                for (int mf = 0; mf < 2; mf++)
#pragma unroll
                    for (int nf = 0; nf < 4; nf++)
                        mma_f16(C[mf][nf],
                                A4[mf][0].z, A4[mf][1].z, A4[mf][0].w, A4[mf][1].w,
                                B4[nf].z, B4[nf].w);
            }

            // ---- flag fast path: fmin(|.|) tree + warp vote ----
#pragma unroll
            for (int mf = 0; mf < 2; mf++) {
                float mn = fabsf(C[mf][0][0]);
#pragma unroll
                for (int nf = 0; nf < 4; nf++)
#pragma unroll
                    for (int idx = 0; idx < 4; idx++)
                        mn = fminf(mn, fabsf(C[mf][nf][idx]));
                if (__any_sync(0xffffffffu, mn < TAU)) {
#pragma unroll
                    for (int nf = 0; nf < 4; nf++)
#pragma unroll
                        for (int idx = 0; idx < 4; idx++) {
                            if (fabsf(C[mf][nf][idx]) < TAU) {
                                int row = rowbase + wm * 32 + mf * 16 + g + ((idx >> 1) ? 8 : 0);
                                int col = n_tile * 256 + h * 128 + wn * 32 + nf * 8
                                          + tq * 2 + (idx & 1);
                                int qi = atomicAdd(qcnt, 1);
                                if (qi < QCAP)
                                    qbuf[qi] = ((uint32_t)isq << 31) |
                                               ((uint32_t)row << 10) | (uint32_t)col;
                            }
                        }
                }
            }

            // ---- provisional sign-pack via shfl-OR over the 4 t-lanes ----
#pragma unroll
            for (int mf = 0; mf < 2; mf++) {
                unsigned m0 = 0, m1 = 0;
#pragma unroll
                for (int nf = 0; nf < 4; nf++) {
                    int p = nf * 8 + tq * 2;
                    m0 |= (C[mf][nf][0] > 0.0f ? 1u : 0u) << p;
                    m0 |= (C[mf][nf][1] > 0.0f ? 1u : 0u) << (p + 1);
                    m1 |= (C[mf][nf][2] > 0.0f ? 1u : 0u) << p;
                    m1 |= (C[mf][nf][3] > 0.0f ? 1u : 0u) << (p + 1);
                }
                m0 |= __shfl_xor_sync(0xffffffffu, m0, 1);
                m0 |= __shfl_xor_sync(0xffffffffu, m0, 2);
                m1 |= __shfl_xor_sync(0xffffffffu, m1, 1);
                m1 |= __shfl_xor_sync(0xffffffffu, m1, 2);
                if (tq == 0) {
                    size_t r0 = (size_t)rowbase + wm * 32 + mf * 16 + g;
                    int wcol = n_tile * 8 + h * 4 + wn;
                    codes[r0 * 32 + wcol]       = m0;
                    codes[(r0 + 8) * 32 + wcol] = m1;
                }
            }
        }
        // stage reuse protected by next iteration's barrier (distance-2 issue)
    }

    // ---- refinement: exact fp32 dot for queued elements, patch bits ----
    __threadfence();
    __syncthreads();
    int nq = *qcnt; if (nq > QCAP) nq = QCAP;
    for (int i = t; i < nq; i += 512) {
        uint32_t e = qbuf[i];
        int isq2 = (int)(e >> 31);
        int row = (int)((e >> 10) & 0xFFFFu), col = (int)(e & 1023u);
        const float* Af = isq2 ? Afq : Afd;
        unsigned* codes = isq2 ? codes_q : codes_d;
        const float4* pa = (const float4*)(Af + (size_t)row * D_DIM);
        const float4* pb = (const float4*)(Bf + (size_t)col * D_DIM);
        float d = 0.0f;
#pragma unroll 8
        for (int w = 0; w < 32; w++) {
            float4 x = pa[w], y = pb[w];
            d += x.x * y.x + x.y * y.y + x.z * y.z + x.w * y.w;
        }
        unsigned* wp = codes + (size_t)row * 32 + (col >> 5);
        unsigned bit = 1u << (col & 31);
        if (d > 0.0f) atomicOr(wp, bit);
        else          atomicAnd(wp, ~bit);
    }
}

// ---------------------------------------------------------------------------
// popcount Hamming -> cos -> masked output in [BAT,L,A,B] layout. (unchanged)
// ---------------------------------------------------------------------------
__global__ __launch_bounds__(256)
void simmat_kernel(const int* __restrict__ qtok,
                   const int* __restrict__ dtok,
                   float* __restrict__ out)
{
    __shared__ unsigned qw[A_DIM][33];
    __shared__ unsigned dw[64][33];
    __shared__ int s1[A_DIM];
    __shared__ int s2[64];
    __shared__ int qm[A_DIM];
    __shared__ int dm[64];

    const int t  = threadIdx.x;
    const int cc = blockIdx.x;
    const int b  = blockIdx.y;
    const int l  = blockIdx.z;

    const unsigned* qbase = g_codes_q + (size_t)(l * BAT + b) * A_DIM * 32;
    const unsigned* dbase = g_codes_d +
        ((size_t)(l * BAT + b) * B_DIM + (size_t)cc * 64) * 32;

#pragma unroll
    for (int f = t; f < 64 * 32; f += 256) {
        int row = f >> 5, w = f & 31;
        qw[row][w] = qbase[f];
        dw[row][w] = dbase[f];
    }
    if (t < 64)        qm[t]      = qtok[b * A_DIM + t];
    else if (t < 128)  dm[t - 64] = dtok[b * B_DIM + cc * 64 + (t - 64)];
    __syncthreads();

    if (t < 64) {
        int s = 0;
#pragma unroll
        for (int w = 0; w < 32; w++) s += __popc(qw[t][w]);
        s1[t] = s;
    } else if (t < 128) {
        int s = 0;
#pragma unroll
        for (int w = 0; w < 32; w++) s += __popc(dw[t - 64][w]);
        s2[t - 64] = s;
    }
    __syncthreads();

    const int ta = t >> 4;
    const int tc = t & 15;
    int dot[4][4];
#pragma unroll
    for (int ai = 0; ai < 4; ai++)
#pragma unroll
        for (int ci = 0; ci < 4; ci++) dot[ai][ci] = 0;

#pragma unroll
    for (int w = 0; w < 32; w++) {
        unsigned qa[4], dc[4];
#pragma unroll
        for (int ai = 0; ai < 4; ai++) qa[ai] = qw[ta + 16 * ai][w];
#pragma unroll
        for (int ci = 0; ci < 4; ci++) dc[ci] = dw[tc + 16 * ci][w];
#pragma unroll
        for (int ai = 0; ai < 4; ai++)
#pragma unroll
            for (int ci = 0; ci < 4; ci++)
                dot[ai][ci] += __popc(qa[ai] & dc[ci]);
    }

    const float kfac = 3.14159265358979323846f / (float)NBITS;
#pragma unroll
    for (int ai = 0; ai < 4; ai++) {
        int a = ta + 16 * ai;
        bool qz = (qm[a] == 0);
        int  sa = s1[a];
        size_t obase = ((((size_t)b * L_DIM + l) * A_DIM + a) * B_DIM)
                       + (size_t)cc * 64;
#pragma unroll
        for (int ci = 0; ci < 4; ci++) {
            int c   = tc + 16 * ci;
            int ham = sa + s2[c] - 2 * dot[ai][ci];
            float v = (qz || dm[c] == 0) ? 0.0f
                                         : __cosf(kfac * (float)ham);
            out[obase + c] = v;
        }
    }
}

// ---------------------------------------------------------------------------
extern "C" void kernel_launch(void* const* d_in, const int* in_sizes, int n_in,
                              void* d_out, int out_size)
{
    const float* qe = (const float*)d_in[0];
    const float* de = (const float*)d_in[1];
    const int*   qt = (const int*)d_in[2];
    const int*   dt = (const int*)d_in[3];
    const float* r  = (const float*)d_in[4];
    float* out = (float*)d_out;

    unsigned *cq = nullptr, *cd = nullptr;
    uint32_t *hq = nullptr, *hd = nullptr, *hr = nullptr;
    cudaGetSymbolAddress((void**)&cq, g_codes_q);
    cudaGetSymbolAddress((void**)&cd, g_codes_d);
    cudaGetSymbolAddress((void**)&hq, g_half_q);
    cudaGetSymbolAddress((void**)&hd, g_half_d);
    cudaGetSymbolAddress((void**)&hr, g_half_r);

    // fp32 -> f16 (fragment-permuted); one thread per (row, ksp)
    split_kernel<<<(4096 * 4 + 255) / 256, 256>>>(qe, hq, 4096 * 4);
    split_kernel<<<(65536 * 4 + 255) / 256, 256>>>(de, hd, 65536 * 4);
    split_kernel<<<(1024 * 4 + 255) / 256, 256>>>(r, hr, 1024 * 4);

    cudaFuncSetAttribute(lsh_hh_kernel,
                         cudaFuncAttributeMaxDynamicSharedMemorySize, SMEMSZ);

    // one launch: 544 m-tiles x 4 n-slices(256 cols), 36 persistent CTAs each
    lsh_hh_kernel<<<dim3(NSL, GRID_Y), 512, SMEMSZ>>>(hd, hq, de, qe, hr, r, cd, cq);

    simmat_kernel<<<dim3(B_DIM / 64, BAT, L_DIM), 256>>>(qt, dt, out);
}